// round 14
// baseline (speedup 1.0000x reference)
#include <cuda_runtime.h>
#include <cuda_fp16.h>
#include <cstdint>
#include <cstddef>

// Problem constants
#define BB 2
#define TT 2048
#define DD 1024
#define HH 16
#define DH 64
#define D3 3072
#define D2 2048
#define NROWS (BB*TT)           // 4096
#define LM_ELEMS (16ull*2048ull*2048ull)  // 67108864

// ---------------------------------------------------------------------------
// Scratch (device globals; no allocation in kernel_launch)
// ---------------------------------------------------------------------------
__device__ __align__(16) __half g_qkv16[(size_t)NROWS * D3];   // fp16 q|k|v
__device__ __align__(16) __half g_x16[(size_t)NROWS * DD];
__device__ __align__(16) __half g_m16[(size_t)NROWS * D2];     // merged
__device__ __align__(16) __half g_wg16[(size_t)D2 * DD];       // Wgate fp16 (natural)
__device__ __align__(16) __half g_msig[LM_ELEMS];              // sigmoid(log_mask) fp16
__device__ float g_partials[2048];                             // reg per-block partials
__device__ float g_bout[DD];                                   // bgate @ Wout

// transposed fp16 weights: [N][K]
__device__ __align__(16) __half g_wqkvT[(size_t)D3 * DD];
__device__ __align__(16) __half g_wcomboT[(size_t)DD * D2];    // (Wgate@Wout)^T [1024][2048]
__device__ __align__(16) __half g_woutT[(size_t)DD * DD];

// ---------------------------------------------------------------------------
// Helpers
// ---------------------------------------------------------------------------
__device__ __forceinline__ uint32_t smem_u32(const void* p) {
    uint32_t a;
    asm("{ .reg .u64 t; cvta.to.shared.u64 t, %1; cvt.u32.u64 %0, t; }" : "=r"(a) : "l"(p));
    return a;
}

#define CP_ASYNC16(dst, src) \
    asm volatile("cp.async.cg.shared.global [%0], [%1], 16;" :: "r"(dst), "l"(src))
#define CP_COMMIT() asm volatile("cp.async.commit_group;" ::: "memory")
#define CP_WAIT(n)  asm volatile("cp.async.wait_group %0;" :: "n"(n) : "memory")

#define LDSM4(R0, R1, R2, R3, addr) \
    asm volatile("ldmatrix.sync.aligned.m8n8.x4.shared.b16 {%0,%1,%2,%3}, [%4];" \
                 : "=r"(R0), "=r"(R1), "=r"(R2), "=r"(R3) : "r"(addr))

#define LDSMT4(R0, R1, R2, R3, addr) \
    asm volatile("ldmatrix.sync.aligned.m8n8.x4.trans.shared.b16 {%0,%1,%2,%3}, [%4];" \
                 : "=r"(R0), "=r"(R1), "=r"(R2), "=r"(R3) : "r"(addr))

#define MMAF16(C, A, B) \
    asm volatile("mma.sync.aligned.m16n8k16.row.col.f32.f16.f16.f32 " \
                 "{%0,%1,%2,%3}, {%4,%5,%6,%7}, {%8,%9}, {%0,%1,%2,%3};" \
                 : "+f"((C)[0]), "+f"((C)[1]), "+f"((C)[2]), "+f"((C)[3]) \
                 : "r"((A)[0]), "r"((A)[1]), "r"((A)[2]), "r"((A)[3]), \
                   "r"((B)[0]), "r"((B)[1]))

__device__ __forceinline__ uint32_t pack_f16x2(float lo, float hi) {
    __half2 h = __floats2half2_rn(lo, hi);   // .x = lo (low half)
    return *reinterpret_cast<uint32_t*>(&h);
}

// FMA-pipe sigmoid; |x|<1 fast path (log_mask ~ N(0,0.1))
__device__ __forceinline__ float fast_sigmoid(float x) {
    if (fabsf(x) < 1.0f) {
        const float t = 0.5f * x;
        const float t2 = t * t;
        float p = 0.021869488f;
        p = fmaf(p, t2, -0.053968254f);
        p = fmaf(p, t2, 0.133333333f);
        p = fmaf(p, t2, -0.333333333f);
        p = fmaf(p, t2, 1.0f);
        return fmaf(0.5f * t, p, 0.5f);
    }
    const float e = __expf(-x);
    return 1.0f / (1.0f + e);
}

// ---------------------------------------------------------------------------
// Utility kernels
// ---------------------------------------------------------------------------
// sigmoid(log_mask) -> fp16 table (lower triangle only) + reg partial sums
__global__ __launch_bounds__(256) void sigmoid_mask_kernel(
    const float* __restrict__ lm, __half* __restrict__ M, float* __restrict__ partials)
{
    __shared__ float sh[256];
    float s = 0.f;
    const float4* lm4 = (const float4*)lm;
    const size_t n4 = LM_ELEMS / 4;
    const size_t stride = (size_t)gridDim.x * 256;
    for (size_t i = (size_t)blockIdx.x * 256 + threadIdx.x; i < n4; i += stride) {
        float4 v = lm4[i];
        const float s0 = fast_sigmoid(v.x);
        const float s1 = fast_sigmoid(v.y);
        const float s2 = fast_sigmoid(v.z);
        const float s3 = fast_sigmoid(v.w);
        s += s0 + s1 + s2 + s3;
        // lower-triangle only (attention's masked-region reads are select-guarded)
        const uint32_t pos = (uint32_t)((i * 4) & (size_t)(TT * TT - 1));
        const uint32_t row = pos >> 11;            // / TT
        const uint32_t colb = pos & (TT - 1);
        if (colb <= row) {
            uint2 o;
            o.x = pack_f16x2(s0, s1);
            o.y = pack_f16x2(s2, s3);
            ((uint2*)M)[i] = o;
        }
    }
    sh[threadIdx.x] = s;
    __syncthreads();
    for (int o = 128; o > 0; o >>= 1) {
        if (threadIdx.x < o) sh[threadIdx.x] += sh[threadIdx.x + o];
        __syncthreads();
    }
    if (threadIdx.x == 0) partials[blockIdx.x] = sh[0];
}

__global__ void finalize_reg_kernel(float* out, int out_size, const float* partials) {
    __shared__ double sh[256];
    double s = 0.0;
    for (int i = threadIdx.x; i < 2048; i += 256) s += (double)partials[i];
    sh[threadIdx.x] = s;
    __syncthreads();
    for (int o = 128; o > 0; o >>= 1) {
        if (threadIdx.x < o) sh[threadIdx.x] += sh[threadIdx.x + o];
        __syncthreads();
    }
    if (threadIdx.x == 0)
        out[out_size - 1] = (float)(0.0005 * sh[0] / (double)LM_ELEMS);
}

// bout[n] = sum_k bgate[k] * Wout[k][n]   (fp32, coalesced over n)
__global__ __launch_bounds__(256) void bias_fold_kernel(
    const float* __restrict__ bgate, const float* __restrict__ Wout,
    float* __restrict__ bout)
{
    const int n = blockIdx.x * 256 + threadIdx.x;   // grid 4 x 256 = 1024
    float s = 0.f;
    for (int k = 0; k < DD; k++)
        s = fmaf(bgate[k], Wout[(size_t)k * DD + n], s);
    bout[n] = s;
}

// fp32 -> fp16 elementwise
__global__ __launch_bounds__(256) void cvt_rows(
    const float* __restrict__ A, __half* __restrict__ X, size_t n4)
{
    const size_t stride = (size_t)gridDim.x * 256;
    for (size_t i = (size_t)blockIdx.x * 256 + threadIdx.x; i < n4; i += stride) {
        float4 v = ((const float4*)A)[i];
        uint2 o;
        o.x = pack_f16x2(v.x, v.y);
        o.y = pack_f16x2(v.z, v.w);
        ((uint2*)X)[i] = o;
    }
}

// Weight transpose to fp16: T[n][k] = fp16(W[k][n])
__global__ __launch_bounds__(256) void transpose_f16(
    const float* __restrict__ W, __half* __restrict__ T, int K, int N)
{
    __shared__ float t[32][33];
    const int bn = blockIdx.x * 32;
    const int bk = blockIdx.y * 32;
    const int tx = threadIdx.x & 31;
    const int ty = threadIdx.x >> 5;
#pragma unroll
    for (int i = 0; i < 4; i++) {
        const int k = ty + i * 8;
        t[k][tx] = W[(size_t)(bk + k) * N + bn + tx];
    }
    __syncthreads();
#pragma unroll
    for (int i = 0; i < 4; i++) {
        const int n = ty + i * 8;
        T[(size_t)(bn + n) * K + bk + tx] = __float2half(t[tx][n]);
    }
}

// ---------------------------------------------------------------------------
// fp16 HMMA GEMM: C[M,N] = A[M,K] @ B^T[N,K] (+bias)
// CTA 128x256, 512 threads = 16 warps (32M x 64N each), BK=64, 2-stage
// cp.async. 144B-pitch rows. Per-warp pattern identical to R7 config;
// 16 warps/SM for latency hiding, half the wave count.
// N must be a multiple of 256, M of 128, K of 64.
// ---------------------------------------------------------------------------
#define GSTAGE 55296            // (A 128x144) + (B 256x144)
#define GEMM_SMEM (2 * GSTAGE)  // 110592

__global__ __launch_bounds__(512, 1) void gemm_f16(
    const __half* __restrict__ A, const __half* __restrict__ B,
    const float* __restrict__ bias,
    float* __restrict__ Cf, __half* __restrict__ Ch,
    int N, int K)
{
    extern __shared__ char smem[];
    const uint32_t sb = smem_u32(smem);
    const int tid = threadIdx.x;
    const int bn = blockIdx.x * 256, bm = blockIdx.y * 128;
    const int lane = tid & 31;
    const int wid = tid >> 5;
    const int wm = wid & 3;       // 4 warps along M (32 rows each)
    const int wn = wid >> 2;      // 4 warps along N (64 cols each)

    auto load_stage = [&](int st, int kc) {
        const int k0 = kc * 64;
        const uint32_t dbase = sb + st * GSTAGE;
#pragma unroll
        for (int i = 0; i < 6; i++) {
            const int e = tid + i * 512;          // 0..3071 16B slots
            if (e < 1024) {                       // A: 128 rows x 8 slots
                const int row = e >> 3, c8 = e & 7;
                CP_ASYNC16(dbase + row * 144 + c8 * 16,
                           A + (size_t)(bm + row) * K + k0 + c8 * 8);
            } else {                              // B: 256 rows x 8 slots
                const int idx = e - 1024;
                const int row = idx >> 3, c8 = idx & 7;
                CP_ASYNC16(dbase + 18432 + row * 144 + c8 * 16,
                           B + (size_t)(bn + row) * K + k0 + c8 * 8);
            }
        }
        CP_COMMIT();
    };

    float acc[2][8][4];
#pragma unroll
    for (int mb = 0; mb < 2; mb++)
#pragma unroll
        for (int nb = 0; nb < 8; nb++)
#pragma unroll
            for (int k = 0; k < 4; k++) acc[mb][nb][k] = 0.f;

    const int NC = K >> 6;
    load_stage(0, 0);
    if (NC > 1) load_stage(1, 1);

    for (int kc = 0; kc < NC; kc++) {
        if (kc + 1 < NC) { CP_WAIT(1); } else { CP_WAIT(0); }
        __syncthreads();
        const uint32_t sA = sb + (kc & 1) * GSTAGE;
        const uint32_t sB = sA + 18432;
#pragma unroll
        for (int ks = 0; ks < 4; ks++) {
            uint32_t a0[2][4], bfr[8][2];
#pragma unroll
            for (int mb = 0; mb < 2; mb++) {
                const uint32_t ad = sA + (wm * 32 + mb * 16 + (lane & 15)) * 144
                                  + ks * 32 + (lane >> 4) * 16;
                LDSM4(a0[mb][0], a0[mb][1], a0[mb][2], a0[mb][3], ad);
            }
#pragma unroll
            for (int nbp = 0; nbp < 4; nbp++) {
                const uint32_t bd = sB + (wn * 64 + nbp * 16 + (lane & 15)) * 144
                                  + ks * 32 + (lane >> 4) * 16;
                uint32_t r0, r1, r2, r3;
                LDSM4(r0, r1, r2, r3, bd);
                bfr[2 * nbp][0] = r0; bfr[2 * nbp][1] = r2;
                bfr[2 * nbp + 1][0] = r1; bfr[2 * nbp + 1][1] = r3;
            }
#pragma unroll
            for (int mb = 0; mb < 2; mb++)
#pragma unroll
                for (int nb = 0; nb < 8; nb++)
                    MMAF16(acc[mb][nb], a0[mb], bfr[nb]);
        }
        __syncthreads();
        if (kc + 2 < NC) load_stage(kc & 1, kc + 2);
    }

    const int rbase = bm + wm * 32 + (lane >> 2);
#pragma unroll
    for (int mb = 0; mb < 2; mb++) {
#pragma unroll
        for (int nb = 0; nb < 8; nb++) {
            const int col = bn + wn * 64 + nb * 8 + (lane & 3) * 2;
            float v0 = acc[mb][nb][0], v1 = acc[mb][nb][1];
            float v2 = acc[mb][nb][2], v3 = acc[mb][nb][3];
            if (bias) {
                const float b0 = bias[col], b1 = bias[col + 1];
                v0 += b0; v1 += b1; v2 += b0; v3 += b1;
            }
            const int ra = rbase + mb * 16;
            const int rb = ra + 8;
            if (Cf) {
                float2 p0; p0.x = v0; p0.y = v1;
                float2 p1; p1.x = v2; p1.y = v3;
                *(float2*)(Cf + (size_t)ra * N + col) = p0;
                *(float2*)(Cf + (size_t)rb * N + col) = p1;
            } else {
                *(uint32_t*)(Ch + (size_t)ra * N + col) = pack_f16x2(v0, v1);
                *(uint32_t*)(Ch + (size_t)rb * N + col) = pack_f16x2(v2, v3);
            }
        }
    }
}

// ---------------------------------------------------------------------------
// Tensor-core dual-stream causal flash attention (R13 structure, unchanged).
// CTA: 128 threads = 4 warps x 16 query rows (64 q-rows/CTA), 2 CTAs/SM,
// 3-stage cp.async KV ring, one barrier per tile, hoisted Q fragments,
// precomputed fp16 sigmoid mask table.
// smem: Q (64x144B) + 3 x [K 64x144 | V 64x144] = 64512 B.
// ---------------------------------------------------------------------------
#define ATT_SMEM 64512
#define AQ_OFF 0
#define KV_OFF 9216
#define KV_STRIDE 18432   // per buffer: K at +0, V at +9216

__global__ __launch_bounds__(128, 2) void attn_mma(
    const __half* __restrict__ qkv,      // [NROWS, 3D] fp16
    const __half* __restrict__ msig,     // [H, T, T] fp16 sigmoid(log_mask)
    __half* __restrict__ mrg)            // [NROWS, 2D] fp16
{
    extern __shared__ char sm[];
    const uint32_t sb = smem_u32(sm);
    const int tid = threadIdx.x;
    const int wq = tid >> 5, lane = tid & 31;
    const int gid = lane >> 2, tig = lane & 3;
    const int b = blockIdx.z, h = blockIdx.y;
    const int qb = (int)(gridDim.x - 1 - blockIdx.x);   // heavy blocks first
    const int q0 = qb * 64;

    auto load_kv = [&](int buf, int kt) {
#pragma unroll
        for (int i = 0; i < 8; i++) {
            const int task = tid + i * 128;       // 0..1023
            const int sel = task >> 9;            // 0:K 1:V
            const int idx = task & 511;
            const int row = idx >> 3, c8 = idx & 7;
            const __half* src = qkv + (size_t)(b * TT + kt * 64 + row) * D3
                              + (sel ? 2 * DD : DD) + h * DH + c8 * 8;
            CP_ASYNC16(sb + KV_OFF + buf * KV_STRIDE + sel * 9216 + row * 144 + c8 * 16, src);
        }
        CP_COMMIT();
    };

    const int ktmax = qb;

    load_kv(0, 0);
    if (ktmax >= 1) load_kv(1, 1);

    // Q tile: 64 rows x 64 halves (direct copy)
#pragma unroll
    for (int i = 0; i < 4; i++) {
        const int task = tid + i * 128;       // 0..511
        const int row = task >> 3, c8 = task & 7;
        const __half* src = qkv + (size_t)(b * TT + q0 + row) * D3 + h * DH + c8 * 8;
        *(uint4*)(sm + AQ_OFF + row * 144 + c8 * 16) = *(const uint4*)src;
    }

    float Ot[8][4], Oc[8][4];
#pragma unroll
    for (int nt = 0; nt < 8; nt++)
#pragma unroll
        for (int j = 0; j < 4; j++) { Ot[nt][j] = 0.f; Oc[nt][j] = 0.f; }
    float lt0 = 0.f, lt1 = 0.f, lc0 = 0.f, lc1 = 0.f;

    const int wrow0 = q0 + wq * 16;
    const int r_lo = wrow0 + gid;
    const int r_hi = r_lo + 8;
    const size_t lmb = (size_t)h * TT * TT;
    const __half* mrow_lo = msig + lmb + (size_t)r_lo * TT;
    const __half* mrow_hi = msig + lmb + (size_t)r_hi * TT;

    uint32_t qf[4][4];
    int cur = 0;

    for (int kt = 0; kt <= ktmax; kt++) {
        if (kt < ktmax) { CP_WAIT(1); } else { CP_WAIT(0); }
        __syncthreads();

        if (kt == 0) {
#pragma unroll
            for (int ks = 0; ks < 4; ks++) {
                const uint32_t qa = sb + AQ_OFF + (wq * 16 + (lane & 15)) * 144
                                  + ks * 32 + (lane >> 4) * 16;
                LDSM4(qf[ks][0], qf[ks][1], qf[ks][2], qf[ks][3], qa);
            }
        }
        if (kt + 2 <= ktmax) load_kv((kt + 2) % 3, kt + 2);

        const uint32_t kbase = sb + KV_OFF + cur * KV_STRIDE;
        const uint32_t vbase = kbase + 9216;
        cur = (cur == 2) ? 0 : cur + 1;

        // QK
        float S[8][4];
#pragma unroll
        for (int nt = 0; nt < 8; nt++)
#pragma unroll
            for (int j = 0; j < 4; j++) S[nt][j] = 0.f;

#pragma unroll
        for (int ks = 0; ks < 4; ks++) {
            uint32_t kb[8][2];
#pragma unroll
            for (int nbp = 0; nbp < 4; nbp++) {
                const uint32_t ka = kbase + (nbp * 16 + (lane & 15)) * 144
                                  + ks * 32 + (lane >> 4) * 16;
                uint32_t r0, r1, r2, r3;
                LDSM4(r0, r1, r2, r3, ka);
                kb[2 * nbp][0] = r0; kb[2 * nbp][1] = r2;
                kb[2 * nbp + 1][0] = r1; kb[2 * nbp + 1][1] = r3;
            }
#pragma unroll
            for (int nt = 0; nt < 8; nt++)
                MMAF16(S[nt], qf[ks], kb[nt]);
        }

        // dual softmax (no-max; bounded scores); precomputed sigmoid table
        float Pc[8][4];
        const bool full = (kt * 64 + 63 <= wrow0);
#pragma unroll
        for (int nt = 0; nt < 8; nt++) {
            const int col = kt * 64 + nt * 8 + 2 * tig;
            const float2 m0 = __half22float2(*(const __half2*)(mrow_lo + col));
            const float2 m1 = __half22float2(*(const __half2*)(mrow_hi + col));
            const float s0 = S[nt][0] * 0.125f;
            const float s1 = S[nt][1] * 0.125f;
            const float s2 = S[nt][2] * 0.125f;
            const float s3 = S[nt][3] * 0.125f;
            float pc0 = __expf(s0 * m0.x);
            float pc1 = __expf(s1 * m0.y);
            float pc2 = __expf(s2 * m1.x);
            float pc3 = __expf(s3 * m1.y);
            float pt0 = __expf(s0);
            float pt1 = __expf(s1);
            float pt2 = __expf(s2);
            float pt3 = __expf(s3);
            if (!full) {
                const bool v0 = (col     <= r_lo), v1 = (col + 1 <= r_lo);
                const bool v2 = (col     <= r_hi), v3 = (col + 1 <= r_hi);
                pt0 = v0 ? pt0 : 0.f; pc0 = v0 ? pc0 : 0.f;
                pt1 = v1 ? pt1 : 0.f; pc1 = v1 ? pc1 : 0.f;
                pt2 = v2 ? pt2 : 0.f; pc2 = v2 ? pc2 : 0.f;
                pt3 = v3 ? pt3 : 0.f; pc3 = v3 ? pc3 : 0.f;
            }
            lt0 += pt0 + pt1; lt1 += pt2 + pt3;
            lc0 += pc0 + pc1; lc1 += pc2 + pc3;
            S[nt][0] = pt0; S[nt][1] = pt1; S[nt][2] = pt2; S[nt][3] = pt3;
            Pc[nt][0] = pc0; Pc[nt][1] = pc1; Pc[nt][2] = pc2; Pc[nt][3] = pc3;
        }

        // PV, both streams, shared V fragments
#pragma unroll
        for (int ks = 0; ks < 4; ks++) {
            uint32_t pth[4], pch[4];
            pth[0] = pack_f16x2(S[2 * ks][0],     S[2 * ks][1]);
            pth[1] = pack_f16x2(S[2 * ks][2],     S[2 * ks][3]);
            pth[2] = pack_f16x2(S[2 * ks + 1][0], S[2 * ks + 1][1]);
            pth[3] = pack_f16x2(S[2 * ks + 1][2], S[2 * ks + 1][3]);
            pch[0] = pack_f16x2(Pc[2 * ks][0],     Pc[2 * ks][1]);
            pch[1] = pack_f16x2(Pc[2 * ks][2],     Pc[2 * ks][3]);
            pch[2] = pack_f16x2(Pc[2 * ks + 1][0], Pc[2 * ks + 1][1]);
            pch[3] = pack_f16x2(Pc[2 * ks + 1][2], Pc[2 * ks + 1][3]);

            uint32_t vb[8][2];
#pragma unroll
            for (int ntp = 0; ntp < 4; ntp++) {
                const uint32_t va = vbase + (ks * 16 + (lane & 15)) * 144
                                  + (2 * ntp + (lane >> 4)) * 16;
                uint32_t r0, r1, r2, r3;
                LDSMT4(r0, r1, r2, r3, va);
                vb[2 * ntp][0] = r0; vb[2 * ntp][1] = r1;
                vb[2 * ntp + 1][0] = r2; vb[2 * ntp + 1][1] = r3;
            }
#pragma unroll
            for (int nt = 0; nt < 8; nt++) {
                MMAF16(Ot[nt], pth, vb[nt]);
                MMAF16(Oc[nt], pch, vb[nt]);
            }
        }
    }

    // epilogue
    lt0 += __shfl_xor_sync(0xffffffffu, lt0, 1); lt0 += __shfl_xor_sync(0xffffffffu, lt0, 2);
    lt1 += __shfl_xor_sync(0xffffffffu, lt1, 1); lt1 += __shfl_xor_sync(0xffffffffu, lt1, 2);
    lc0 += __shfl_xor_sync(0xffffffffu, lc0, 1); lc0 += __shfl_xor_sync(0xffffffffu, lc0, 2);
    lc1 += __shfl_xor_sync(0xffffffffu, lc1, 1); lc1 += __shfl_xor_sync(0xffffffffu, lc1, 2);
    const float it0 = 1.f / lt0, it1 = 1.f / lt1;
    const float ic0 = 1.f / lc0, ic1 = 1.f / lc1;

    const size_t rowa = (size_t)(b * TT + r_lo);
    const size_t rowb = (size_t)(b * TT + r_hi);
#pragma unroll
    for (int nt = 0; nt < 8; nt++) {
        const int col = h * DH + nt * 8 + 2 * tig;
        *(uint32_t*)(mrg + rowa * D2 + col)      = pack_f16x2(Ot[nt][0] * it0, Ot[nt][1] * it0);
        *(uint32_t*)(mrg + rowb * D2 + col)      = pack_f16x2(Ot[nt][2] * it1, Ot[nt][3] * it1);
        *(uint32_t*)(mrg + rowa * D2 + DD + col) = pack_f16x2(Oc[nt][0] * ic0, Oc[nt][1] * ic0);
        *(uint32_t*)(mrg + rowb * D2 + DD + col) = pack_f16x2(Oc[nt][2] * ic1, Oc[nt][3] * ic1);
    }
}

// ---------------------------------------------------------------------------
// Launch  (gemm_f16(qkv) kept 4th -> gets profiled; new 512-thr config)
// ---------------------------------------------------------------------------
extern "C" void kernel_launch(void* const* d_in, const int* in_sizes, int n_in,
                              void* d_out, int out_size) {
    const float* x        = (const float*)d_in[0];
    // d_in[1] = causal_mask — deterministic, handled analytically
    const float* Wqkv     = (const float*)d_in[2];
    const float* log_mask = (const float*)d_in[3];
    const float* Wgate    = (const float*)d_in[4];
    const float* bgate    = (const float*)d_in[5];
    const float* Wout     = (const float*)d_in[6];
    float* out = (float*)d_out;

    __half *qkv16, *x16, *m16, *wg16, *msig, *wqkvT, *wcomboT, *woutT;
    float *partials, *bout;
    cudaGetSymbolAddress((void**)&qkv16,   g_qkv16);
    cudaGetSymbolAddress((void**)&x16,     g_x16);
    cudaGetSymbolAddress((void**)&m16,     g_m16);
    cudaGetSymbolAddress((void**)&wg16,    g_wg16);
    cudaGetSymbolAddress((void**)&msig,    g_msig);
    cudaGetSymbolAddress((void**)&partials, g_partials);
    cudaGetSymbolAddress((void**)&bout,    g_bout);
    cudaGetSymbolAddress((void**)&wqkvT,   g_wqkvT);
    cudaGetSymbolAddress((void**)&wcomboT, g_wcomboT);
    cudaGetSymbolAddress((void**)&woutT,   g_woutT);

    cudaFuncSetAttribute(gemm_f16, cudaFuncAttributeMaxDynamicSharedMemorySize, GEMM_SMEM);
    cudaFuncSetAttribute(attn_mma, cudaFuncAttributeMaxDynamicSharedMemorySize, ATT_SMEM);

    // 1: mask sigmoid table + reg partials
    sigmoid_mask_kernel<<<2048, 256>>>(log_mask, msig, partials);
    // 2-3: qkv producers
    transpose_f16<<<dim3(D3 / 32, DD / 32), 256>>>(Wqkv, wqkvT, DD, D3);
    cvt_rows<<<512, 256>>>(x, x16, (size_t)NROWS * DD / 4);
    // 4: qkv GEMM (profiled): [4096,1024] @ [1024,3072]
    gemm_f16<<<dim3(D3 / 256, NROWS / 128), 512, GEMM_SMEM>>>(
        x16, wqkvT, nullptr, nullptr, qkv16, D3, DD);
    // 5: attention
    attn_mma<<<dim3(TT / 64, HH, BB), 128, ATT_SMEM>>>(qkv16, msig, m16);

    // fused tail prep: WcomboT = WoutT @ Wgate (C[m][n] = sum_j WoutT[m][j]*Wgate[n][j])
    transpose_f16<<<dim3(DD / 32, DD / 32), 256>>>(Wout, woutT, DD, DD);
    cvt_rows<<<512, 256>>>(Wgate, wg16, (size_t)D2 * DD / 4);
    gemm_f16<<<dim3(D2 / 256, DD / 128), 512, GEMM_SMEM>>>(
        woutT, wg16, nullptr, nullptr, wcomboT, D2, DD);
    bias_fold_kernel<<<4, 256>>>(bgate, Wout, bout);

    // out = merged @ Wcombo + bout : [4096,2048] @ [2048,1024] (fp32 out)
    gemm_f16<<<dim3(DD / 256, NROWS / 128), 512, GEMM_SMEM>>>(
        m16, wcomboT, bout, out, nullptr, DD, D2);

    finalize_reg_kernel<<<1, 256>>>(out, out_size, partials);
}

// round 15
// speedup vs baseline: 1.0510x; 1.0510x over previous
#include <cuda_runtime.h>
#include <cuda_fp16.h>
#include <cstdint>
#include <cstddef>

// Problem constants
#define BB 2
#define TT 2048
#define DD 1024
#define HH 16
#define DH 64
#define D3 3072
#define D2 2048
#define NROWS (BB*TT)           // 4096
#define LM_ELEMS (16ull*2048ull*2048ull)  // 67108864

// ---------------------------------------------------------------------------
// Scratch (device globals; no allocation in kernel_launch)
// ---------------------------------------------------------------------------
__device__ __align__(16) __half g_qkv16[(size_t)NROWS * D3];   // fp16 q|k|v
__device__ __align__(16) __half g_x16[(size_t)NROWS * DD];
__device__ __align__(16) __half g_m16[(size_t)NROWS * D2];     // merged
__device__ __align__(16) __half g_wg16[(size_t)D2 * DD];       // Wgate fp16 (natural)
__device__ __align__(16) __half g_msig[LM_ELEMS];              // sigmoid(log_mask) fp16
__device__ float g_partials[2048];                             // reg per-block partials
__device__ float g_bout[DD];                                   // bgate @ Wout

// transposed fp16 weights: [N][K]
__device__ __align__(16) __half g_wqkvT[(size_t)D3 * DD];
__device__ __align__(16) __half g_wcomboT[(size_t)DD * D2];    // (Wgate@Wout)^T [1024][2048]
__device__ __align__(16) __half g_woutT[(size_t)DD * DD];

// ---------------------------------------------------------------------------
// Helpers
// ---------------------------------------------------------------------------
__device__ __forceinline__ uint32_t smem_u32(const void* p) {
    uint32_t a;
    asm("{ .reg .u64 t; cvta.to.shared.u64 t, %1; cvt.u32.u64 %0, t; }" : "=r"(a) : "l"(p));
    return a;
}

#define CP_ASYNC16(dst, src) \
    asm volatile("cp.async.cg.shared.global [%0], [%1], 16;" :: "r"(dst), "l"(src))
#define CP_COMMIT() asm volatile("cp.async.commit_group;" ::: "memory")
#define CP_WAIT(n)  asm volatile("cp.async.wait_group %0;" :: "n"(n) : "memory")

#define LDSM4(R0, R1, R2, R3, addr) \
    asm volatile("ldmatrix.sync.aligned.m8n8.x4.shared.b16 {%0,%1,%2,%3}, [%4];" \
                 : "=r"(R0), "=r"(R1), "=r"(R2), "=r"(R3) : "r"(addr))

#define LDSMT4(R0, R1, R2, R3, addr) \
    asm volatile("ldmatrix.sync.aligned.m8n8.x4.trans.shared.b16 {%0,%1,%2,%3}, [%4];" \
                 : "=r"(R0), "=r"(R1), "=r"(R2), "=r"(R3) : "r"(addr))

#define MMAF16(C, A, B) \
    asm volatile("mma.sync.aligned.m16n8k16.row.col.f32.f16.f16.f32 " \
                 "{%0,%1,%2,%3}, {%4,%5,%6,%7}, {%8,%9}, {%0,%1,%2,%3};" \
                 : "+f"((C)[0]), "+f"((C)[1]), "+f"((C)[2]), "+f"((C)[3]) \
                 : "r"((A)[0]), "r"((A)[1]), "r"((A)[2]), "r"((A)[3]), \
                   "r"((B)[0]), "r"((B)[1]))

__device__ __forceinline__ uint32_t pack_f16x2(float lo, float hi) {
    __half2 h = __floats2half2_rn(lo, hi);   // .x = lo (low half)
    return *reinterpret_cast<uint32_t*>(&h);
}

// FMA-pipe sigmoid; |x|<1 fast path (log_mask ~ N(0,0.1))
__device__ __forceinline__ float fast_sigmoid(float x) {
    if (fabsf(x) < 1.0f) {
        const float t = 0.5f * x;
        const float t2 = t * t;
        float p = 0.021869488f;
        p = fmaf(p, t2, -0.053968254f);
        p = fmaf(p, t2, 0.133333333f);
        p = fmaf(p, t2, -0.333333333f);
        p = fmaf(p, t2, 1.0f);
        return fmaf(0.5f * t, p, 0.5f);
    }
    const float e = __expf(-x);
    return 1.0f / (1.0f + e);
}

// ---------------------------------------------------------------------------
// Utility kernels
// ---------------------------------------------------------------------------
// sigmoid(log_mask) -> fp16 table (lower triangle only) + reg partial sums
__global__ __launch_bounds__(256) void sigmoid_mask_kernel(
    const float* __restrict__ lm, __half* __restrict__ M, float* __restrict__ partials)
{
    __shared__ float sh[256];
    float s = 0.f;
    const float4* lm4 = (const float4*)lm;
    const size_t n4 = LM_ELEMS / 4;
    const size_t stride = (size_t)gridDim.x * 256;
    for (size_t i = (size_t)blockIdx.x * 256 + threadIdx.x; i < n4; i += stride) {
        float4 v = lm4[i];
        const float s0 = fast_sigmoid(v.x);
        const float s1 = fast_sigmoid(v.y);
        const float s2 = fast_sigmoid(v.z);
        const float s3 = fast_sigmoid(v.w);
        s += s0 + s1 + s2 + s3;
        // lower-triangle only (attention's masked-region reads are select-guarded)
        const uint32_t pos = (uint32_t)((i * 4) & (size_t)(TT * TT - 1));
        const uint32_t row = pos >> 11;            // / TT
        const uint32_t colb = pos & (TT - 1);
        if (colb <= row) {
            uint2 o;
            o.x = pack_f16x2(s0, s1);
            o.y = pack_f16x2(s2, s3);
            ((uint2*)M)[i] = o;
        }
    }
    sh[threadIdx.x] = s;
    __syncthreads();
    for (int o = 128; o > 0; o >>= 1) {
        if (threadIdx.x < o) sh[threadIdx.x] += sh[threadIdx.x + o];
        __syncthreads();
    }
    if (threadIdx.x == 0) partials[blockIdx.x] = sh[0];
}

__global__ void finalize_reg_kernel(float* out, int out_size, const float* partials) {
    __shared__ double sh[256];
    double s = 0.0;
    for (int i = threadIdx.x; i < 2048; i += 256) s += (double)partials[i];
    sh[threadIdx.x] = s;
    __syncthreads();
    for (int o = 128; o > 0; o >>= 1) {
        if (threadIdx.x < o) sh[threadIdx.x] += sh[threadIdx.x + o];
        __syncthreads();
    }
    if (threadIdx.x == 0)
        out[out_size - 1] = (float)(0.0005 * sh[0] / (double)LM_ELEMS);
}

// bout[n] = sum_k bgate[k] * Wout[k][n]   (fp32, coalesced over n)
__global__ __launch_bounds__(256) void bias_fold_kernel(
    const float* __restrict__ bgate, const float* __restrict__ Wout,
    float* __restrict__ bout)
{
    const int n = blockIdx.x * 256 + threadIdx.x;   // grid 4 x 256 = 1024
    float s = 0.f;
    for (int k = 0; k < DD; k++)
        s = fmaf(bgate[k], Wout[(size_t)k * DD + n], s);
    bout[n] = s;
}

// fp32 -> fp16 elementwise
__global__ __launch_bounds__(256) void cvt_rows(
    const float* __restrict__ A, __half* __restrict__ X, size_t n4)
{
    const size_t stride = (size_t)gridDim.x * 256;
    for (size_t i = (size_t)blockIdx.x * 256 + threadIdx.x; i < n4; i += stride) {
        float4 v = ((const float4*)A)[i];
        uint2 o;
        o.x = pack_f16x2(v.x, v.y);
        o.y = pack_f16x2(v.z, v.w);
        ((uint2*)X)[i] = o;
    }
}

// Weight transpose to fp16: T[n][k] = fp16(W[k][n])
__global__ __launch_bounds__(256) void transpose_f16(
    const float* __restrict__ W, __half* __restrict__ T, int K, int N)
{
    __shared__ float t[32][33];
    const int bn = blockIdx.x * 32;
    const int bk = blockIdx.y * 32;
    const int tx = threadIdx.x & 31;
    const int ty = threadIdx.x >> 5;
#pragma unroll
    for (int i = 0; i < 4; i++) {
        const int k = ty + i * 8;
        t[k][tx] = W[(size_t)(bk + k) * N + bn + tx];
    }
    __syncthreads();
#pragma unroll
    for (int i = 0; i < 4; i++) {
        const int n = ty + i * 8;
        T[(size_t)(bn + n) * K + bk + tx] = __float2half(t[tx][n]);
    }
}

// ---------------------------------------------------------------------------
// fp16 HMMA GEMM: C[M,N] = A[M,K] @ B^T[N,K] (+bias)
// CTA 128x128, BK=64, 3-stage cp.async pipeline, 8 warps (32M x 64N each).
// 144B-pitch rows. (R13-measured-best config: 110.5us on qkv, tensor 43.6%.)
// ---------------------------------------------------------------------------
#define GSTAGE 36864            // (A 128x144) + (B 128x144)
#define GEMM_SMEM (3 * GSTAGE)  // 110592

__global__ __launch_bounds__(256, 1) void gemm_f16(
    const __half* __restrict__ A, const __half* __restrict__ B,
    const float* __restrict__ bias,
    float* __restrict__ Cf, __half* __restrict__ Ch,
    int N, int K)
{
    extern __shared__ char smem[];
    const uint32_t sb = smem_u32(smem);
    const int tid = threadIdx.x;
    const int bn = blockIdx.x * 128, bm = blockIdx.y * 128;
    const int lane = tid & 31;
    const int wid = tid >> 5;
    const int wm = wid & 3;       // 4 warps along M
    const int wn = wid >> 2;      // 2 warps along N

    auto load_stage = [&](int st, int kc) {
        const int k0 = kc * 64;
        const uint32_t dbase = sb + st * GSTAGE;
#pragma unroll
        for (int i = 0; i < 8; i++) {
            const int e = tid + i * 256;          // 0..2047
            const int sel = e >> 10;              // 0:A 1:B
            const int idx = e & 1023;
            const int row = idx >> 3;
            const int c8 = idx & 7;
            const __half* src = (sel ? B + (size_t)(bn + row) * K
                                     : A + (size_t)(bm + row) * K) + k0 + c8 * 8;
            CP_ASYNC16(dbase + sel * 18432 + row * 144 + c8 * 16, src);
        }
        CP_COMMIT();
    };

    float acc[2][8][4];
#pragma unroll
    for (int mb = 0; mb < 2; mb++)
#pragma unroll
        for (int nb = 0; nb < 8; nb++)
#pragma unroll
            for (int k = 0; k < 4; k++) acc[mb][nb][k] = 0.f;

    const int NC = K >> 6;
    load_stage(0, 0);
    load_stage(1, 1);
    load_stage(2, 2);

    int st = 0;
    for (int kc = 0; kc < NC; kc++) {
        const int rem = NC - 1 - kc;
        if (rem >= 2) { CP_WAIT(2); } else if (rem == 1) { CP_WAIT(1); } else { CP_WAIT(0); }
        __syncthreads();
        const uint32_t sA = sb + st * GSTAGE;
        const uint32_t sB = sA + 18432;
#pragma unroll
        for (int ks = 0; ks < 4; ks++) {
            uint32_t a0[2][4], bfr[8][2];
#pragma unroll
            for (int mb = 0; mb < 2; mb++) {
                const uint32_t ad = sA + (wm * 32 + mb * 16 + (lane & 15)) * 144
                                  + ks * 32 + (lane >> 4) * 16;
                LDSM4(a0[mb][0], a0[mb][1], a0[mb][2], a0[mb][3], ad);
            }
#pragma unroll
            for (int nbp = 0; nbp < 4; nbp++) {
                const uint32_t bd = sB + (wn * 64 + nbp * 16 + (lane & 15)) * 144
                                  + ks * 32 + (lane >> 4) * 16;
                uint32_t r0, r1, r2, r3;
                LDSM4(r0, r1, r2, r3, bd);
                bfr[2 * nbp][0] = r0; bfr[2 * nbp][1] = r2;
                bfr[2 * nbp + 1][0] = r1; bfr[2 * nbp + 1][1] = r3;
            }
#pragma unroll
            for (int mb = 0; mb < 2; mb++)
#pragma unroll
                for (int nb = 0; nb < 8; nb++)
                    MMAF16(acc[mb][nb], a0[mb], bfr[nb]);
        }
        __syncthreads();
        if (kc + 3 < NC) load_stage(st, kc + 3);
        st = (st == 2) ? 0 : st + 1;
    }

    const int rbase = bm + wm * 32 + (lane >> 2);
#pragma unroll
    for (int mb = 0; mb < 2; mb++) {
#pragma unroll
        for (int nb = 0; nb < 8; nb++) {
            const int col = bn + wn * 64 + nb * 8 + (lane & 3) * 2;
            float v0 = acc[mb][nb][0], v1 = acc[mb][nb][1];
            float v2 = acc[mb][nb][2], v3 = acc[mb][nb][3];
            if (bias) {
                const float b0 = bias[col], b1 = bias[col + 1];
                v0 += b0; v1 += b1; v2 += b0; v3 += b1;
            }
            const int ra = rbase + mb * 16;
            const int rb = ra + 8;
            if (Cf) {
                float2 p0; p0.x = v0; p0.y = v1;
                float2 p1; p1.x = v2; p1.y = v3;
                *(float2*)(Cf + (size_t)ra * N + col) = p0;
                *(float2*)(Cf + (size_t)rb * N + col) = p1;
            } else {
                *(uint32_t*)(Ch + (size_t)ra * N + col) = pack_f16x2(v0, v1);
                *(uint32_t*)(Ch + (size_t)rb * N + col) = pack_f16x2(v2, v3);
            }
        }
    }
}

// ---------------------------------------------------------------------------
// Tensor-core dual-stream causal flash attention (R13 structure, unchanged).
// CTA: 128 threads = 4 warps x 16 query rows (64 q-rows/CTA), 2 CTAs/SM,
// 3-stage cp.async KV ring, one barrier per tile, hoisted Q fragments,
// precomputed fp16 sigmoid mask table.
// smem: Q (64x144B) + 3 x [K 64x144 | V 64x144] = 64512 B.
// ---------------------------------------------------------------------------
#define ATT_SMEM 64512
#define AQ_OFF 0
#define KV_OFF 9216
#define KV_STRIDE 18432   // per buffer: K at +0, V at +9216

__global__ __launch_bounds__(128, 2) void attn_mma(
    const __half* __restrict__ qkv,      // [NROWS, 3D] fp16
    const __half* __restrict__ msig,     // [H, T, T] fp16 sigmoid(log_mask)
    __half* __restrict__ mrg)            // [NROWS, 2D] fp16
{
    extern __shared__ char sm[];
    const uint32_t sb = smem_u32(sm);
    const int tid = threadIdx.x;
    const int wq = tid >> 5, lane = tid & 31;
    const int gid = lane >> 2, tig = lane & 3;
    const int b = blockIdx.z, h = blockIdx.y;
    const int qb = (int)(gridDim.x - 1 - blockIdx.x);   // heavy blocks first
    const int q0 = qb * 64;

    auto load_kv = [&](int buf, int kt) {
#pragma unroll
        for (int i = 0; i < 8; i++) {
            const int task = tid + i * 128;       // 0..1023
            const int sel = task >> 9;            // 0:K 1:V
            const int idx = task & 511;
            const int row = idx >> 3, c8 = idx & 7;
            const __half* src = qkv + (size_t)(b * TT + kt * 64 + row) * D3
                              + (sel ? 2 * DD : DD) + h * DH + c8 * 8;
            CP_ASYNC16(sb + KV_OFF + buf * KV_STRIDE + sel * 9216 + row * 144 + c8 * 16, src);
        }
        CP_COMMIT();
    };

    const int ktmax = qb;

    load_kv(0, 0);
    if (ktmax >= 1) load_kv(1, 1);

    // Q tile: 64 rows x 64 halves (direct copy)
#pragma unroll
    for (int i = 0; i < 4; i++) {
        const int task = tid + i * 128;       // 0..511
        const int row = task >> 3, c8 = task & 7;
        const __half* src = qkv + (size_t)(b * TT + q0 + row) * D3 + h * DH + c8 * 8;
        *(uint4*)(sm + AQ_OFF + row * 144 + c8 * 16) = *(const uint4*)src;
    }

    float Ot[8][4], Oc[8][4];
#pragma unroll
    for (int nt = 0; nt < 8; nt++)
#pragma unroll
        for (int j = 0; j < 4; j++) { Ot[nt][j] = 0.f; Oc[nt][j] = 0.f; }
    float lt0 = 0.f, lt1 = 0.f, lc0 = 0.f, lc1 = 0.f;

    const int wrow0 = q0 + wq * 16;
    const int r_lo = wrow0 + gid;
    const int r_hi = r_lo + 8;
    const size_t lmb = (size_t)h * TT * TT;
    const __half* mrow_lo = msig + lmb + (size_t)r_lo * TT;
    const __half* mrow_hi = msig + lmb + (size_t)r_hi * TT;

    uint32_t qf[4][4];
    int cur = 0;

    for (int kt = 0; kt <= ktmax; kt++) {
        if (kt < ktmax) { CP_WAIT(1); } else { CP_WAIT(0); }
        __syncthreads();

        if (kt == 0) {
#pragma unroll
            for (int ks = 0; ks < 4; ks++) {
                const uint32_t qa = sb + AQ_OFF + (wq * 16 + (lane & 15)) * 144
                                  + ks * 32 + (lane >> 4) * 16;
                LDSM4(qf[ks][0], qf[ks][1], qf[ks][2], qf[ks][3], qa);
            }
        }
        if (kt + 2 <= ktmax) load_kv((kt + 2) % 3, kt + 2);

        const uint32_t kbase = sb + KV_OFF + cur * KV_STRIDE;
        const uint32_t vbase = kbase + 9216;
        cur = (cur == 2) ? 0 : cur + 1;

        // QK
        float S[8][4];
#pragma unroll
        for (int nt = 0; nt < 8; nt++)
#pragma unroll
            for (int j = 0; j < 4; j++) S[nt][j] = 0.f;

#pragma unroll
        for (int ks = 0; ks < 4; ks++) {
            uint32_t kb[8][2];
#pragma unroll
            for (int nbp = 0; nbp < 4; nbp++) {
                const uint32_t ka = kbase + (nbp * 16 + (lane & 15)) * 144
                                  + ks * 32 + (lane >> 4) * 16;
                uint32_t r0, r1, r2, r3;
                LDSM4(r0, r1, r2, r3, ka);
                kb[2 * nbp][0] = r0; kb[2 * nbp][1] = r2;
                kb[2 * nbp + 1][0] = r1; kb[2 * nbp + 1][1] = r3;
            }
#pragma unroll
            for (int nt = 0; nt < 8; nt++)
                MMAF16(S[nt], qf[ks], kb[nt]);
        }

        // dual softmax (no-max; bounded scores); precomputed sigmoid table
        float Pc[8][4];
        const bool full = (kt * 64 + 63 <= wrow0);
#pragma unroll
        for (int nt = 0; nt < 8; nt++) {
            const int col = kt * 64 + nt * 8 + 2 * tig;
            const float2 m0 = __half22float2(*(const __half2*)(mrow_lo + col));
            const float2 m1 = __half22float2(*(const __half2*)(mrow_hi + col));
            const float s0 = S[nt][0] * 0.125f;
            const float s1 = S[nt][1] * 0.125f;
            const float s2 = S[nt][2] * 0.125f;
            const float s3 = S[nt][3] * 0.125f;
            float pc0 = __expf(s0 * m0.x);
            float pc1 = __expf(s1 * m0.y);
            float pc2 = __expf(s2 * m1.x);
            float pc3 = __expf(s3 * m1.y);
            float pt0 = __expf(s0);
            float pt1 = __expf(s1);
            float pt2 = __expf(s2);
            float pt3 = __expf(s3);
            if (!full) {
                const bool v0 = (col     <= r_lo), v1 = (col + 1 <= r_lo);
                const bool v2 = (col     <= r_hi), v3 = (col + 1 <= r_hi);
                pt0 = v0 ? pt0 : 0.f; pc0 = v0 ? pc0 : 0.f;
                pt1 = v1 ? pt1 : 0.f; pc1 = v1 ? pc1 : 0.f;
                pt2 = v2 ? pt2 : 0.f; pc2 = v2 ? pc2 : 0.f;
                pt3 = v3 ? pt3 : 0.f; pc3 = v3 ? pc3 : 0.f;
            }
            lt0 += pt0 + pt1; lt1 += pt2 + pt3;
            lc0 += pc0 + pc1; lc1 += pc2 + pc3;
            S[nt][0] = pt0; S[nt][1] = pt1; S[nt][2] = pt2; S[nt][3] = pt3;
            Pc[nt][0] = pc0; Pc[nt][1] = pc1; Pc[nt][2] = pc2; Pc[nt][3] = pc3;
        }

        // PV, both streams, shared V fragments
#pragma unroll
        for (int ks = 0; ks < 4; ks++) {
            uint32_t pth[4], pch[4];
            pth[0] = pack_f16x2(S[2 * ks][0],     S[2 * ks][1]);
            pth[1] = pack_f16x2(S[2 * ks][2],     S[2 * ks][3]);
            pth[2] = pack_f16x2(S[2 * ks + 1][0], S[2 * ks + 1][1]);
            pth[3] = pack_f16x2(S[2 * ks + 1][2], S[2 * ks + 1][3]);
            pch[0] = pack_f16x2(Pc[2 * ks][0],     Pc[2 * ks][1]);
            pch[1] = pack_f16x2(Pc[2 * ks][2],     Pc[2 * ks][3]);
            pch[2] = pack_f16x2(Pc[2 * ks + 1][0], Pc[2 * ks + 1][1]);
            pch[3] = pack_f16x2(Pc[2 * ks + 1][2], Pc[2 * ks + 1][3]);

            uint32_t vb[8][2];
#pragma unroll
            for (int ntp = 0; ntp < 4; ntp++) {
                const uint32_t va = vbase + (ks * 16 + (lane & 15)) * 144
                                  + (2 * ntp + (lane >> 4)) * 16;
                uint32_t r0, r1, r2, r3;
                LDSMT4(r0, r1, r2, r3, va);
                vb[2 * ntp][0] = r0; vb[2 * ntp][1] = r1;
                vb[2 * ntp + 1][0] = r2; vb[2 * ntp + 1][1] = r3;
            }
#pragma unroll
            for (int nt = 0; nt < 8; nt++) {
                MMAF16(Ot[nt], pth, vb[nt]);
                MMAF16(Oc[nt], pch, vb[nt]);
            }
        }
    }

    // epilogue
    lt0 += __shfl_xor_sync(0xffffffffu, lt0, 1); lt0 += __shfl_xor_sync(0xffffffffu, lt0, 2);
    lt1 += __shfl_xor_sync(0xffffffffu, lt1, 1); lt1 += __shfl_xor_sync(0xffffffffu, lt1, 2);
    lc0 += __shfl_xor_sync(0xffffffffu, lc0, 1); lc0 += __shfl_xor_sync(0xffffffffu, lc0, 2);
    lc1 += __shfl_xor_sync(0xffffffffu, lc1, 1); lc1 += __shfl_xor_sync(0xffffffffu, lc1, 2);
    const float it0 = 1.f / lt0, it1 = 1.f / lt1;
    const float ic0 = 1.f / lc0, ic1 = 1.f / lc1;

    const size_t rowa = (size_t)(b * TT + r_lo);
    const size_t rowb = (size_t)(b * TT + r_hi);
#pragma unroll
    for (int nt = 0; nt < 8; nt++) {
        const int col = h * DH + nt * 8 + 2 * tig;
        *(uint32_t*)(mrg + rowa * D2 + col)      = pack_f16x2(Ot[nt][0] * it0, Ot[nt][1] * it0);
        *(uint32_t*)(mrg + rowb * D2 + col)      = pack_f16x2(Ot[nt][2] * it1, Ot[nt][3] * it1);
        *(uint32_t*)(mrg + rowa * D2 + DD + col) = pack_f16x2(Oc[nt][0] * ic0, Oc[nt][1] * ic0);
        *(uint32_t*)(mrg + rowb * D2 + DD + col) = pack_f16x2(Oc[nt][2] * ic1, Oc[nt][3] * ic1);
    }
}

// ---------------------------------------------------------------------------
// Launch  (gemm_f16(qkv) 4th -> profiled, confirming config revert)
// ---------------------------------------------------------------------------
extern "C" void kernel_launch(void* const* d_in, const int* in_sizes, int n_in,
                              void* d_out, int out_size) {
    const float* x        = (const float*)d_in[0];
    // d_in[1] = causal_mask — deterministic, handled analytically
    const float* Wqkv     = (const float*)d_in[2];
    const float* log_mask = (const float*)d_in[3];
    const float* Wgate    = (const float*)d_in[4];
    const float* bgate    = (const float*)d_in[5];
    const float* Wout     = (const float*)d_in[6];
    float* out = (float*)d_out;

    __half *qkv16, *x16, *m16, *wg16, *msig, *wqkvT, *wcomboT, *woutT;
    float *partials, *bout;
    cudaGetSymbolAddress((void**)&qkv16,   g_qkv16);
    cudaGetSymbolAddress((void**)&x16,     g_x16);
    cudaGetSymbolAddress((void**)&m16,     g_m16);
    cudaGetSymbolAddress((void**)&wg16,    g_wg16);
    cudaGetSymbolAddress((void**)&msig,    g_msig);
    cudaGetSymbolAddress((void**)&partials, g_partials);
    cudaGetSymbolAddress((void**)&bout,    g_bout);
    cudaGetSymbolAddress((void**)&wqkvT,   g_wqkvT);
    cudaGetSymbolAddress((void**)&wcomboT, g_wcomboT);
    cudaGetSymbolAddress((void**)&woutT,   g_woutT);

    cudaFuncSetAttribute(gemm_f16, cudaFuncAttributeMaxDynamicSharedMemorySize, GEMM_SMEM);
    cudaFuncSetAttribute(attn_mma, cudaFuncAttributeMaxDynamicSharedMemorySize, ATT_SMEM);

    // 1: mask sigmoid table + reg partials
    sigmoid_mask_kernel<<<2048, 256>>>(log_mask, msig, partials);
    // 2-3: qkv producers
    transpose_f16<<<dim3(D3 / 32, DD / 32), 256>>>(Wqkv, wqkvT, DD, D3);
    cvt_rows<<<512, 256>>>(x, x16, (size_t)NROWS * DD / 4);
    // 4: qkv GEMM (profiled): [4096,1024] @ [1024,3072]
    gemm_f16<<<dim3(D3 / 128, NROWS / 128), 256, GEMM_SMEM>>>(
        x16, wqkvT, nullptr, nullptr, qkv16, D3, DD);
    // 5: attention
    attn_mma<<<dim3(TT / 64, HH, BB), 128, ATT_SMEM>>>(qkv16, msig, m16);

    // fused tail prep: WcomboT = WoutT @ Wgate (C[m][n] = sum_j WoutT[m][j]*Wgate[n][j])
    transpose_f16<<<dim3(DD / 32, DD / 32), 256>>>(Wout, woutT, DD, DD);
    cvt_rows<<<512, 256>>>(Wgate, wg16, (size_t)D2 * DD / 4);
    gemm_f16<<<dim3(D2 / 128, DD / 128), 256, GEMM_SMEM>>>(
        woutT, wg16, nullptr, nullptr, wcomboT, D2, DD);
    bias_fold_kernel<<<4, 256>>>(bgate, Wout, bout);

    // out = merged @ Wcombo + bout : [4096,2048] @ [2048,1024] (fp32 out)
    gemm_f16<<<dim3(DD / 128, NROWS / 128), 256, GEMM_SMEM>>>(
        m16, wcomboT, bout, out, nullptr, DD, D2);

    finalize_reg_kernel<<<1, 256>>>(out, out_size, partials);
}

// round 16
// speedup vs baseline: 1.1118x; 1.0579x over previous
#include <cuda_runtime.h>
#include <cuda_fp16.h>
#include <cstdint>
#include <cstddef>

// Problem constants
#define BB 2
#define TT 2048
#define DD 1024
#define HH 16
#define DH 64
#define D3 3072
#define D2 2048
#define NROWS (BB*TT)           // 4096
#define LM_ELEMS (16ull*2048ull*2048ull)  // 67108864

// ---------------------------------------------------------------------------
// Scratch (device globals; no allocation in kernel_launch)
// ---------------------------------------------------------------------------
__device__ __align__(16) __half g_qkv16[(size_t)NROWS * D3];   // fp16 q|k|v
__device__ __align__(16) __half g_x16[(size_t)NROWS * DD];
__device__ __align__(16) __half g_m16[(size_t)NROWS * D2];     // merged
__device__ __align__(16) __half g_wg16[(size_t)D2 * DD];       // Wgate fp16 (natural)
__device__ __align__(16) __half g_msig[LM_ELEMS];              // sigmoid(log_mask) fp16
__device__ float g_partials[2048];                             // reg per-block partials
__device__ float g_bout[DD];                                   // bgate @ Wout

// transposed fp16 weights: [N][K]
__device__ __align__(16) __half g_wqkvT[(size_t)D3 * DD];
__device__ __align__(16) __half g_wcomboT[(size_t)DD * D2];    // (Wgate@Wout)^T [1024][2048]
__device__ __align__(16) __half g_woutT[(size_t)DD * DD];

// ---------------------------------------------------------------------------
// Helpers
// ---------------------------------------------------------------------------
__device__ __forceinline__ uint32_t smem_u32(const void* p) {
    uint32_t a;
    asm("{ .reg .u64 t; cvta.to.shared.u64 t, %1; cvt.u32.u64 %0, t; }" : "=r"(a) : "l"(p));
    return a;
}

#define CP_ASYNC16(dst, src) \
    asm volatile("cp.async.cg.shared.global [%0], [%1], 16;" :: "r"(dst), "l"(src))
#define CP_COMMIT() asm volatile("cp.async.commit_group;" ::: "memory")
#define CP_WAIT(n)  asm volatile("cp.async.wait_group %0;" :: "n"(n) : "memory")

#define LDSM4(R0, R1, R2, R3, addr) \
    asm volatile("ldmatrix.sync.aligned.m8n8.x4.shared.b16 {%0,%1,%2,%3}, [%4];" \
                 : "=r"(R0), "=r"(R1), "=r"(R2), "=r"(R3) : "r"(addr))

#define LDSMT4(R0, R1, R2, R3, addr) \
    asm volatile("ldmatrix.sync.aligned.m8n8.x4.trans.shared.b16 {%0,%1,%2,%3}, [%4];" \
                 : "=r"(R0), "=r"(R1), "=r"(R2), "=r"(R3) : "r"(addr))

#define MMAF16(C, A, B) \
    asm volatile("mma.sync.aligned.m16n8k16.row.col.f32.f16.f16.f32 " \
                 "{%0,%1,%2,%3}, {%4,%5,%6,%7}, {%8,%9}, {%0,%1,%2,%3};" \
                 : "+f"((C)[0]), "+f"((C)[1]), "+f"((C)[2]), "+f"((C)[3]) \
                 : "r"((A)[0]), "r"((A)[1]), "r"((A)[2]), "r"((A)[3]), \
                   "r"((B)[0]), "r"((B)[1]))

__device__ __forceinline__ uint32_t pack_f16x2(float lo, float hi) {
    __half2 h = __floats2half2_rn(lo, hi);   // .x = lo (low half)
    return *reinterpret_cast<uint32_t*>(&h);
}

// FMA-pipe sigmoid; |x|<1 fast path (log_mask ~ N(0,0.1))
__device__ __forceinline__ float fast_sigmoid(float x) {
    if (fabsf(x) < 1.0f) {
        const float t = 0.5f * x;
        const float t2 = t * t;
        float p = 0.021869488f;
        p = fmaf(p, t2, -0.053968254f);
        p = fmaf(p, t2, 0.133333333f);
        p = fmaf(p, t2, -0.333333333f);
        p = fmaf(p, t2, 1.0f);
        return fmaf(0.5f * t, p, 0.5f);
    }
    const float e = __expf(-x);
    return 1.0f / (1.0f + e);
}

// ---------------------------------------------------------------------------
// Utility kernels
// ---------------------------------------------------------------------------
// sigmoid(log_mask) -> fp16 table (lower triangle only) + reg partial sums
__global__ __launch_bounds__(256) void sigmoid_mask_kernel(
    const float* __restrict__ lm, __half* __restrict__ M, float* __restrict__ partials)
{
    __shared__ float sh[256];
    float s = 0.f;
    const float4* lm4 = (const float4*)lm;
    const size_t n4 = LM_ELEMS / 4;
    const size_t stride = (size_t)gridDim.x * 256;
    for (size_t i = (size_t)blockIdx.x * 256 + threadIdx.x; i < n4; i += stride) {
        float4 v = lm4[i];
        const float s0 = fast_sigmoid(v.x);
        const float s1 = fast_sigmoid(v.y);
        const float s2 = fast_sigmoid(v.z);
        const float s3 = fast_sigmoid(v.w);
        s += s0 + s1 + s2 + s3;
        // lower-triangle only (attention's masked-region reads are select-guarded)
        const uint32_t pos = (uint32_t)((i * 4) & (size_t)(TT * TT - 1));
        const uint32_t row = pos >> 11;            // / TT
        const uint32_t colb = pos & (TT - 1);
        if (colb <= row) {
            uint2 o;
            o.x = pack_f16x2(s0, s1);
            o.y = pack_f16x2(s2, s3);
            ((uint2*)M)[i] = o;
        }
    }
    sh[threadIdx.x] = s;
    __syncthreads();
    for (int o = 128; o > 0; o >>= 1) {
        if (threadIdx.x < o) sh[threadIdx.x] += sh[threadIdx.x + o];
        __syncthreads();
    }
    if (threadIdx.x == 0) partials[blockIdx.x] = sh[0];
}

__global__ void finalize_reg_kernel(float* out, int out_size, const float* partials) {
    __shared__ double sh[256];
    double s = 0.0;
    for (int i = threadIdx.x; i < 2048; i += 256) s += (double)partials[i];
    sh[threadIdx.x] = s;
    __syncthreads();
    for (int o = 128; o > 0; o >>= 1) {
        if (threadIdx.x < o) sh[threadIdx.x] += sh[threadIdx.x + o];
        __syncthreads();
    }
    if (threadIdx.x == 0)
        out[out_size - 1] = (float)(0.0005 * sh[0] / (double)LM_ELEMS);
}

// bout[n] = sum_k bgate[k] * Wout[k][n]  — parallel GEMV.
// Grid 32 x 256 thr: block owns 32 columns; 8 warp-slices split k (128 each,
// coalesced row segments); smem reduction combines slices.
__global__ __launch_bounds__(256) void bias_fold_kernel(
    const float* __restrict__ bgate, const float* __restrict__ Wout,
    float* __restrict__ bout)
{
    __shared__ float sh[8][32];
    const int lane = threadIdx.x & 31;
    const int ks = threadIdx.x >> 5;            // 0..7
    const int n = blockIdx.x * 32 + lane;
    float s = 0.f;
    const int k0 = ks * 128;
#pragma unroll 4
    for (int k = k0; k < k0 + 128; k++)
        s = fmaf(bgate[k], Wout[(size_t)k * DD + n], s);
    sh[ks][lane] = s;
    __syncthreads();
    if (ks == 0) {
        float t = sh[0][lane];
#pragma unroll
        for (int j = 1; j < 8; j++) t += sh[j][lane];
        bout[n] = t;
    }
}

// fp32 -> fp16 elementwise
__global__ __launch_bounds__(256) void cvt_rows(
    const float* __restrict__ A, __half* __restrict__ X, size_t n4)
{
    const size_t stride = (size_t)gridDim.x * 256;
    for (size_t i = (size_t)blockIdx.x * 256 + threadIdx.x; i < n4; i += stride) {
        float4 v = ((const float4*)A)[i];
        uint2 o;
        o.x = pack_f16x2(v.x, v.y);
        o.y = pack_f16x2(v.z, v.w);
        ((uint2*)X)[i] = o;
    }
}

// Weight transpose to fp16: T[n][k] = fp16(W[k][n])
__global__ __launch_bounds__(256) void transpose_f16(
    const float* __restrict__ W, __half* __restrict__ T, int K, int N)
{
    __shared__ float t[32][33];
    const int bn = blockIdx.x * 32;
    const int bk = blockIdx.y * 32;
    const int tx = threadIdx.x & 31;
    const int ty = threadIdx.x >> 5;
#pragma unroll
    for (int i = 0; i < 4; i++) {
        const int k = ty + i * 8;
        t[k][tx] = W[(size_t)(bk + k) * N + bn + tx];
    }
    __syncthreads();
#pragma unroll
    for (int i = 0; i < 4; i++) {
        const int n = ty + i * 8;
        T[(size_t)(bn + n) * K + bk + tx] = __float2half(t[tx][n]);
    }
}

// ---------------------------------------------------------------------------
// fp16 HMMA GEMM: C[M,N] = A[M,K] @ B^T[N,K] (+bias)
// CTA 128x128, BK=64, 3-stage cp.async pipeline, 8 warps (32M x 64N each).
// 144B-pitch rows. (Measured-best config: 106us on qkv, tensor 43.3%.)
// ---------------------------------------------------------------------------
#define GSTAGE 36864            // (A 128x144) + (B 128x144)
#define GEMM_SMEM (3 * GSTAGE)  // 110592

__global__ __launch_bounds__(256, 1) void gemm_f16(
    const __half* __restrict__ A, const __half* __restrict__ B,
    const float* __restrict__ bias,
    float* __restrict__ Cf, __half* __restrict__ Ch,
    int N, int K)
{
    extern __shared__ char smem[];
    const uint32_t sb = smem_u32(smem);
    const int tid = threadIdx.x;
    const int bn = blockIdx.x * 128, bm = blockIdx.y * 128;
    const int lane = tid & 31;
    const int wid = tid >> 5;
    const int wm = wid & 3;       // 4 warps along M
    const int wn = wid >> 2;      // 2 warps along N

    auto load_stage = [&](int st, int kc) {
        const int k0 = kc * 64;
        const uint32_t dbase = sb + st * GSTAGE;
#pragma unroll
        for (int i = 0; i < 8; i++) {
            const int e = tid + i * 256;          // 0..2047
            const int sel = e >> 10;              // 0:A 1:B
            const int idx = e & 1023;
            const int row = idx >> 3;
            const int c8 = idx & 7;
            const __half* src = (sel ? B + (size_t)(bn + row) * K
                                     : A + (size_t)(bm + row) * K) + k0 + c8 * 8;
            CP_ASYNC16(dbase + sel * 18432 + row * 144 + c8 * 16, src);
        }
        CP_COMMIT();
    };

    float acc[2][8][4];
#pragma unroll
    for (int mb = 0; mb < 2; mb++)
#pragma unroll
        for (int nb = 0; nb < 8; nb++)
#pragma unroll
            for (int k = 0; k < 4; k++) acc[mb][nb][k] = 0.f;

    const int NC = K >> 6;
    load_stage(0, 0);
    load_stage(1, 1);
    load_stage(2, 2);

    int st = 0;
    for (int kc = 0; kc < NC; kc++) {
        const int rem = NC - 1 - kc;
        if (rem >= 2) { CP_WAIT(2); } else if (rem == 1) { CP_WAIT(1); } else { CP_WAIT(0); }
        __syncthreads();
        const uint32_t sA = sb + st * GSTAGE;
        const uint32_t sB = sA + 18432;
#pragma unroll
        for (int ks = 0; ks < 4; ks++) {
            uint32_t a0[2][4], bfr[8][2];
#pragma unroll
            for (int mb = 0; mb < 2; mb++) {
                const uint32_t ad = sA + (wm * 32 + mb * 16 + (lane & 15)) * 144
                                  + ks * 32 + (lane >> 4) * 16;
                LDSM4(a0[mb][0], a0[mb][1], a0[mb][2], a0[mb][3], ad);
            }
#pragma unroll
            for (int nbp = 0; nbp < 4; nbp++) {
                const uint32_t bd = sB + (wn * 64 + nbp * 16 + (lane & 15)) * 144
                                  + ks * 32 + (lane >> 4) * 16;
                uint32_t r0, r1, r2, r3;
                LDSM4(r0, r1, r2, r3, bd);
                bfr[2 * nbp][0] = r0; bfr[2 * nbp][1] = r2;
                bfr[2 * nbp + 1][0] = r1; bfr[2 * nbp + 1][1] = r3;
            }
#pragma unroll
            for (int mb = 0; mb < 2; mb++)
#pragma unroll
                for (int nb = 0; nb < 8; nb++)
                    MMAF16(acc[mb][nb], a0[mb], bfr[nb]);
        }
        __syncthreads();
        if (kc + 3 < NC) load_stage(st, kc + 3);
        st = (st == 2) ? 0 : st + 1;
    }

    const int rbase = bm + wm * 32 + (lane >> 2);
#pragma unroll
    for (int mb = 0; mb < 2; mb++) {
#pragma unroll
        for (int nb = 0; nb < 8; nb++) {
            const int col = bn + wn * 64 + nb * 8 + (lane & 3) * 2;
            float v0 = acc[mb][nb][0], v1 = acc[mb][nb][1];
            float v2 = acc[mb][nb][2], v3 = acc[mb][nb][3];
            if (bias) {
                const float b0 = bias[col], b1 = bias[col + 1];
                v0 += b0; v1 += b1; v2 += b0; v3 += b1;
            }
            const int ra = rbase + mb * 16;
            const int rb = ra + 8;
            if (Cf) {
                float2 p0; p0.x = v0; p0.y = v1;
                float2 p1; p1.x = v2; p1.y = v3;
                *(float2*)(Cf + (size_t)ra * N + col) = p0;
                *(float2*)(Cf + (size_t)rb * N + col) = p1;
            } else {
                *(uint32_t*)(Ch + (size_t)ra * N + col) = pack_f16x2(v0, v1);
                *(uint32_t*)(Ch + (size_t)rb * N + col) = pack_f16x2(v2, v3);
            }
        }
    }
}

// ---------------------------------------------------------------------------
// Tensor-core dual-stream causal flash attention (R13 structure, unchanged).
// CTA: 128 threads = 4 warps x 16 query rows (64 q-rows/CTA), 2 CTAs/SM,
// 3-stage cp.async KV ring, one barrier per tile, hoisted Q fragments,
// precomputed fp16 sigmoid mask table.
// smem: Q (64x144B) + 3 x [K 64x144 | V 64x144] = 64512 B.
// ---------------------------------------------------------------------------
#define ATT_SMEM 64512
#define AQ_OFF 0
#define KV_OFF 9216
#define KV_STRIDE 18432   // per buffer: K at +0, V at +9216

__global__ __launch_bounds__(128, 2) void attn_mma(
    const __half* __restrict__ qkv,      // [NROWS, 3D] fp16
    const __half* __restrict__ msig,     // [H, T, T] fp16 sigmoid(log_mask)
    __half* __restrict__ mrg)            // [NROWS, 2D] fp16
{
    extern __shared__ char sm[];
    const uint32_t sb = smem_u32(sm);
    const int tid = threadIdx.x;
    const int wq = tid >> 5, lane = tid & 31;
    const int gid = lane >> 2, tig = lane & 3;
    const int b = blockIdx.z, h = blockIdx.y;
    const int qb = (int)(gridDim.x - 1 - blockIdx.x);   // heavy blocks first
    const int q0 = qb * 64;

    auto load_kv = [&](int buf, int kt) {
#pragma unroll
        for (int i = 0; i < 8; i++) {
            const int task = tid + i * 128;       // 0..1023
            const int sel = task >> 9;            // 0:K 1:V
            const int idx = task & 511;
            const int row = idx >> 3, c8 = idx & 7;
            const __half* src = qkv + (size_t)(b * TT + kt * 64 + row) * D3
                              + (sel ? 2 * DD : DD) + h * DH + c8 * 8;
            CP_ASYNC16(sb + KV_OFF + buf * KV_STRIDE + sel * 9216 + row * 144 + c8 * 16, src);
        }
        CP_COMMIT();
    };

    const int ktmax = qb;

    load_kv(0, 0);
    if (ktmax >= 1) load_kv(1, 1);

    // Q tile: 64 rows x 64 halves (direct copy)
#pragma unroll
    for (int i = 0; i < 4; i++) {
        const int task = tid + i * 128;       // 0..511
        const int row = task >> 3, c8 = task & 7;
        const __half* src = qkv + (size_t)(b * TT + q0 + row) * D3 + h * DH + c8 * 8;
        *(uint4*)(sm + AQ_OFF + row * 144 + c8 * 16) = *(const uint4*)src;
    }

    float Ot[8][4], Oc[8][4];
#pragma unroll
    for (int nt = 0; nt < 8; nt++)
#pragma unroll
        for (int j = 0; j < 4; j++) { Ot[nt][j] = 0.f; Oc[nt][j] = 0.f; }
    float lt0 = 0.f, lt1 = 0.f, lc0 = 0.f, lc1 = 0.f;

    const int wrow0 = q0 + wq * 16;
    const int r_lo = wrow0 + gid;
    const int r_hi = r_lo + 8;
    const size_t lmb = (size_t)h * TT * TT;
    const __half* mrow_lo = msig + lmb + (size_t)r_lo * TT;
    const __half* mrow_hi = msig + lmb + (size_t)r_hi * TT;

    uint32_t qf[4][4];
    int cur = 0;

    for (int kt = 0; kt <= ktmax; kt++) {
        if (kt < ktmax) { CP_WAIT(1); } else { CP_WAIT(0); }
        __syncthreads();

        if (kt == 0) {
#pragma unroll
            for (int ks = 0; ks < 4; ks++) {
                const uint32_t qa = sb + AQ_OFF + (wq * 16 + (lane & 15)) * 144
                                  + ks * 32 + (lane >> 4) * 16;
                LDSM4(qf[ks][0], qf[ks][1], qf[ks][2], qf[ks][3], qa);
            }
        }
        if (kt + 2 <= ktmax) load_kv((kt + 2) % 3, kt + 2);

        const uint32_t kbase = sb + KV_OFF + cur * KV_STRIDE;
        const uint32_t vbase = kbase + 9216;
        cur = (cur == 2) ? 0 : cur + 1;

        // QK
        float S[8][4];
#pragma unroll
        for (int nt = 0; nt < 8; nt++)
#pragma unroll
            for (int j = 0; j < 4; j++) S[nt][j] = 0.f;

#pragma unroll
        for (int ks = 0; ks < 4; ks++) {
            uint32_t kb[8][2];
#pragma unroll
            for (int nbp = 0; nbp < 4; nbp++) {
                const uint32_t ka = kbase + (nbp * 16 + (lane & 15)) * 144
                                  + ks * 32 + (lane >> 4) * 16;
                uint32_t r0, r1, r2, r3;
                LDSM4(r0, r1, r2, r3, ka);
                kb[2 * nbp][0] = r0; kb[2 * nbp][1] = r2;
                kb[2 * nbp + 1][0] = r1; kb[2 * nbp + 1][1] = r3;
            }
#pragma unroll
            for (int nt = 0; nt < 8; nt++)
                MMAF16(S[nt], qf[ks], kb[nt]);
        }

        // dual softmax (no-max; bounded scores); precomputed sigmoid table
        float Pc[8][4];
        const bool full = (kt * 64 + 63 <= wrow0);
#pragma unroll
        for (int nt = 0; nt < 8; nt++) {
            const int col = kt * 64 + nt * 8 + 2 * tig;
            const float2 m0 = __half22float2(*(const __half2*)(mrow_lo + col));
            const float2 m1 = __half22float2(*(const __half2*)(mrow_hi + col));
            const float s0 = S[nt][0] * 0.125f;
            const float s1 = S[nt][1] * 0.125f;
            const float s2 = S[nt][2] * 0.125f;
            const float s3 = S[nt][3] * 0.125f;
            float pc0 = __expf(s0 * m0.x);
            float pc1 = __expf(s1 * m0.y);
            float pc2 = __expf(s2 * m1.x);
            float pc3 = __expf(s3 * m1.y);
            float pt0 = __expf(s0);
            float pt1 = __expf(s1);
            float pt2 = __expf(s2);
            float pt3 = __expf(s3);
            if (!full) {
                const bool v0 = (col     <= r_lo), v1 = (col + 1 <= r_lo);
                const bool v2 = (col     <= r_hi), v3 = (col + 1 <= r_hi);
                pt0 = v0 ? pt0 : 0.f; pc0 = v0 ? pc0 : 0.f;
                pt1 = v1 ? pt1 : 0.f; pc1 = v1 ? pc1 : 0.f;
                pt2 = v2 ? pt2 : 0.f; pc2 = v2 ? pc2 : 0.f;
                pt3 = v3 ? pt3 : 0.f; pc3 = v3 ? pc3 : 0.f;
            }
            lt0 += pt0 + pt1; lt1 += pt2 + pt3;
            lc0 += pc0 + pc1; lc1 += pc2 + pc3;
            S[nt][0] = pt0; S[nt][1] = pt1; S[nt][2] = pt2; S[nt][3] = pt3;
            Pc[nt][0] = pc0; Pc[nt][1] = pc1; Pc[nt][2] = pc2; Pc[nt][3] = pc3;
        }

        // PV, both streams, shared V fragments
#pragma unroll
        for (int ks = 0; ks < 4; ks++) {
            uint32_t pth[4], pch[4];
            pth[0] = pack_f16x2(S[2 * ks][0],     S[2 * ks][1]);
            pth[1] = pack_f16x2(S[2 * ks][2],     S[2 * ks][3]);
            pth[2] = pack_f16x2(S[2 * ks + 1][0], S[2 * ks + 1][1]);
            pth[3] = pack_f16x2(S[2 * ks + 1][2], S[2 * ks + 1][3]);
            pch[0] = pack_f16x2(Pc[2 * ks][0],     Pc[2 * ks][1]);
            pch[1] = pack_f16x2(Pc[2 * ks][2],     Pc[2 * ks][3]);
            pch[2] = pack_f16x2(Pc[2 * ks + 1][0], Pc[2 * ks + 1][1]);
            pch[3] = pack_f16x2(Pc[2 * ks + 1][2], Pc[2 * ks + 1][3]);

            uint32_t vb[8][2];
#pragma unroll
            for (int ntp = 0; ntp < 4; ntp++) {
                const uint32_t va = vbase + (ks * 16 + (lane & 15)) * 144
                                  + (2 * ntp + (lane >> 4)) * 16;
                uint32_t r0, r1, r2, r3;
                LDSMT4(r0, r1, r2, r3, va);
                vb[2 * ntp][0] = r0; vb[2 * ntp][1] = r1;
                vb[2 * ntp + 1][0] = r2; vb[2 * ntp + 1][1] = r3;
            }
#pragma unroll
            for (int nt = 0; nt < 8; nt++) {
                MMAF16(Ot[nt], pth, vb[nt]);
                MMAF16(Oc[nt], pch, vb[nt]);
            }
        }
    }

    // epilogue
    lt0 += __shfl_xor_sync(0xffffffffu, lt0, 1); lt0 += __shfl_xor_sync(0xffffffffu, lt0, 2);
    lt1 += __shfl_xor_sync(0xffffffffu, lt1, 1); lt1 += __shfl_xor_sync(0xffffffffu, lt1, 2);
    lc0 += __shfl_xor_sync(0xffffffffu, lc0, 1); lc0 += __shfl_xor_sync(0xffffffffu, lc0, 2);
    lc1 += __shfl_xor_sync(0xffffffffu, lc1, 1); lc1 += __shfl_xor_sync(0xffffffffu, lc1, 2);
    const float it0 = 1.f / lt0, it1 = 1.f / lt1;
    const float ic0 = 1.f / lc0, ic1 = 1.f / lc1;

    const size_t rowa = (size_t)(b * TT + r_lo);
    const size_t rowb = (size_t)(b * TT + r_hi);
#pragma unroll
    for (int nt = 0; nt < 8; nt++) {
        const int col = h * DH + nt * 8 + 2 * tig;
        *(uint32_t*)(mrg + rowa * D2 + col)      = pack_f16x2(Ot[nt][0] * it0, Ot[nt][1] * it0);
        *(uint32_t*)(mrg + rowb * D2 + col)      = pack_f16x2(Ot[nt][2] * it1, Ot[nt][3] * it1);
        *(uint32_t*)(mrg + rowa * D2 + DD + col) = pack_f16x2(Oc[nt][0] * ic0, Oc[nt][1] * ic0);
        *(uint32_t*)(mrg + rowb * D2 + DD + col) = pack_f16x2(Oc[nt][2] * ic1, Oc[nt][3] * ic1);
    }
}

// ---------------------------------------------------------------------------
// Launch  (gemm_f16(qkv) 4th -> profiled)
// ---------------------------------------------------------------------------
extern "C" void kernel_launch(void* const* d_in, const int* in_sizes, int n_in,
                              void* d_out, int out_size) {
    const float* x        = (const float*)d_in[0];
    // d_in[1] = causal_mask — deterministic, handled analytically
    const float* Wqkv     = (const float*)d_in[2];
    const float* log_mask = (const float*)d_in[3];
    const float* Wgate    = (const float*)d_in[4];
    const float* bgate    = (const float*)d_in[5];
    const float* Wout     = (const float*)d_in[6];
    float* out = (float*)d_out;

    __half *qkv16, *x16, *m16, *wg16, *msig, *wqkvT, *wcomboT, *woutT;
    float *partials, *bout;
    cudaGetSymbolAddress((void**)&qkv16,   g_qkv16);
    cudaGetSymbolAddress((void**)&x16,     g_x16);
    cudaGetSymbolAddress((void**)&m16,     g_m16);
    cudaGetSymbolAddress((void**)&wg16,    g_wg16);
    cudaGetSymbolAddress((void**)&msig,    g_msig);
    cudaGetSymbolAddress((void**)&partials, g_partials);
    cudaGetSymbolAddress((void**)&bout,    g_bout);
    cudaGetSymbolAddress((void**)&wqkvT,   g_wqkvT);
    cudaGetSymbolAddress((void**)&wcomboT, g_wcomboT);
    cudaGetSymbolAddress((void**)&woutT,   g_woutT);

    cudaFuncSetAttribute(gemm_f16, cudaFuncAttributeMaxDynamicSharedMemorySize, GEMM_SMEM);
    cudaFuncSetAttribute(attn_mma, cudaFuncAttributeMaxDynamicSharedMemorySize, ATT_SMEM);

    // 1: mask sigmoid table + reg partials
    sigmoid_mask_kernel<<<2048, 256>>>(log_mask, msig, partials);
    // 2-3: qkv producers
    transpose_f16<<<dim3(D3 / 32, DD / 32), 256>>>(Wqkv, wqkvT, DD, D3);
    cvt_rows<<<512, 256>>>(x, x16, (size_t)NROWS * DD / 4);
    // 4: qkv GEMM (profiled): [4096,1024] @ [1024,3072]
    gemm_f16<<<dim3(D3 / 128, NROWS / 128), 256, GEMM_SMEM>>>(
        x16, wqkvT, nullptr, nullptr, qkv16, D3, DD);
    // 5: attention
    attn_mma<<<dim3(TT / 64, HH, BB), 128, ATT_SMEM>>>(qkv16, msig, m16);

    // fused tail prep: WcomboT = WoutT @ Wgate (C[m][n] = sum_j WoutT[m][j]*Wgate[n][j])
    transpose_f16<<<dim3(DD / 32, DD / 32), 256>>>(Wout, woutT, DD, DD);
    cvt_rows<<<512, 256>>>(Wgate, wg16, (size_t)D2 * DD / 4);
    gemm_f16<<<dim3(D2 / 128, DD / 128), 256, GEMM_SMEM>>>(
        woutT, wg16, nullptr, nullptr, wcomboT, D2, DD);
    bias_fold_kernel<<<32, 256>>>(bgate, Wout, bout);

    // out = merged @ Wcombo + bout : [4096,2048] @ [2048,1024] (fp32 out)
    gemm_f16<<<dim3(DD / 128, NROWS / 128), 256, GEMM_SMEM>>>(
        m16, wcomboT, bout, out, nullptr, DD, D2);

    finalize_reg_kernel<<<1, 256>>>(out, out_size, partials);
}